// round 11
// baseline (speedup 1.0000x reference)
#include <cuda_runtime.h>
#include <cstdint>
#include <math.h>

// N=8 (7 completed blocks + partial), D=2048, B*L=8192 rows.
// TMA bulk stage-in with EIGHT mbarrier phases (one per 8KB slice):
// compute on slice n starts as soon as its 8KB lands and overlaps the
// arrivals of slices n+1..7. Monotone trend: 1/2/4 phases = 98.8/97.4/94.9us.
#define NB 8
#define DDIM 2048
#define THREADS 256
#define ROW_BYTES (DDIM * 4)              // 8 KB per block slice
#define SMEM_BYTES (NB * DDIM * 4)        // 64 KB data stage

__device__ __forceinline__ void mbar_wait(unsigned int mb) {
    unsigned int done;
    asm volatile(
        "{\n\t"
        ".reg .pred p;\n\t"
        "mbarrier.try_wait.parity.acquire.cta.shared::cta.b64 p, [%1], 0;\n\t"
        "selp.b32 %0, 1, 0, p;\n\t"
        "}" : "=r"(done) : "r"(mb) : "memory");
    if (!done) {
        asm volatile(
            "{\n\t"
            ".reg .pred P1;\n\t"
            "WAIT_LOOP_%=:\n\t"
            "mbarrier.try_wait.parity.acquire.cta.shared::cta.b64 P1, [%0], 0, 0x989680;\n\t"
            "@P1 bra.uni WAIT_DONE_%=;\n\t"
            "bra.uni WAIT_LOOP_%=;\n\t"
            "WAIT_DONE_%=:\n\t"
            "}" :: "r"(mb) : "memory");
    }
}

__global__ __launch_bounds__(THREADS, 3)
void attn_residual_kernel(const float* __restrict__ blocks,     // [7, BL, D]
                          const float* __restrict__ partial,    // [BL, D]
                          const float* __restrict__ norm_scale, // [D]
                          const float* __restrict__ proj,       // [D]
                          float* __restrict__ out,              // [BL, D]
                          int BL)
{
    extern __shared__ float sv[];         // [NB][DDIM], 16B aligned
    __shared__ __align__(8) unsigned long long mbar[NB];
    __shared__ float red[THREADS / 32][16];
    __shared__ float fin[16];

    const int row  = blockIdx.x;
    const int t    = threadIdx.x;
    const int lane = t & 31;
    const int warp = t >> 5;

    const size_t rowOff  = (size_t)row * DDIM;
    const size_t nStride = (size_t)BL * DDIM;

    const int d0 = t * 4;            // [0, 1024)
    const int d1 = 1024 + t * 4;     // [1024, 2048)

    unsigned int svb, mbb;
    asm("{ .reg .u64 tmp; cvta.to.shared.u64 tmp, %1; cvt.u32.u64 %0, tmp; }"
        : "=r"(svb) : "l"(sv));
    asm("{ .reg .u64 tmp; cvta.to.shared.u64 tmp, %1; cvt.u32.u64 %0, tmp; }"
        : "=r"(mbb) : "l"(&mbar[0]));

    // ---- Init mbarriers, then bulk-copy 8 contiguous 8KB slices ----
    if (t == 0) {
#pragma unroll
        for (int p = 0; p < NB; p++)
            asm volatile("mbarrier.init.shared.b64 [%0], 1;"
                         :: "r"(mbb + 8u * p) : "memory");
    }
    __syncthreads();

    if (t == 0) {
#pragma unroll
        for (int n = 0; n < NB; n++) {
            const float* src = (n < NB - 1)
                                 ? (blocks + (size_t)n * nStride + rowOff)
                                 : (partial + rowOff);
            asm volatile("mbarrier.arrive.expect_tx.shared.b64 _, [%0], %1;"
                         :: "r"(mbb + 8u * n), "r"(ROW_BYTES) : "memory");
            asm volatile(
                "cp.async.bulk.shared::cluster.global.mbarrier::complete_tx::bytes"
                " [%0], [%1], %2, [%3];"
                :: "r"(svb + (unsigned)(n * ROW_BYTES)), "l"(src),
                   "r"(ROW_BYTES), "r"(mbb + 8u * n)
                : "memory");
        }
    }

    // q[d] = proj[d] * norm_scale[d] (overlaps with bulk copies)
    float4 q0, q1;
    {
        float4 p = *(const float4*)(proj + d0);
        float4 s = *(const float4*)(norm_scale + d0);
        q0 = make_float4(p.x * s.x, p.y * s.y, p.z * s.z, p.w * s.w);
        p = *(const float4*)(proj + d1);
        s = *(const float4*)(norm_scale + d1);
        q1 = make_float4(p.x * s.x, p.y * s.y, p.z * s.z, p.w * s.w);
    }

    float dotp[NB], ssq[NB];

#define PHASE(n)                                                             \
    do {                                                                     \
        mbar_wait(mbb + 8u * (n));                                           \
        float4 a = *(const float4*)(sv + (n) * DDIM + d0);                   \
        float4 b = *(const float4*)(sv + (n) * DDIM + d1);                   \
        dotp[n] = q0.x * a.x + q0.y * a.y + q0.z * a.z + q0.w * a.w          \
                + q1.x * b.x + q1.y * b.y + q1.z * b.z + q1.w * b.w;         \
        ssq[n]  = a.x * a.x + a.y * a.y + a.z * a.z + a.w * a.w              \
                + b.x * b.x + b.y * b.y + b.z * b.z + b.w * b.w;             \
        _Pragma("unroll")                                                    \
        for (int o = 16; o > 0; o >>= 1) {                                   \
            dotp[n] += __shfl_down_sync(0xffffffffu, dotp[n], o);            \
            ssq[n]  += __shfl_down_sync(0xffffffffu, ssq[n],  o);            \
        }                                                                    \
    } while (0)

    PHASE(0); PHASE(1); PHASE(2); PHASE(3);
    PHASE(4); PHASE(5); PHASE(6); PHASE(7);
#undef PHASE

    // ---- Cross-warp reduction of 16 scalars ----
    if (lane == 0) {
#pragma unroll
        for (int n = 0; n < NB; n++) {
            red[warp][n]     = dotp[n];
            red[warp][8 + n] = ssq[n];
        }
    }
    __syncthreads();
    if (t < 16) {
        float s = 0.f;
#pragma unroll
        for (int w = 0; w < THREADS / 32; w++) s += red[w][t];
        fin[t] = s;
    }
    __syncthreads();

    // ---- Softmax over n (redundant per-thread; trivial) ----
    float wgt[NB];
    float mx = -INFINITY;
#pragma unroll
    for (int n = 0; n < NB; n++) {
        float rms = sqrtf(fin[8 + n] * (1.0f / DDIM) + 1e-6f);
        wgt[n] = fin[n] / rms;
        mx = fmaxf(mx, wgt[n]);
    }
    float wsum = 0.f;
#pragma unroll
    for (int n = 0; n < NB; n++) {
        wgt[n] = __expf(wgt[n] - mx);
        wsum += wgt[n];
    }
    const float inv = 1.0f / wsum;

    // ---- Pass 2: weighted sum from smem; streaming store ----
    float4 o0 = make_float4(0.f, 0.f, 0.f, 0.f);
    float4 o1 = make_float4(0.f, 0.f, 0.f, 0.f);
#pragma unroll
    for (int n = 0; n < NB; n++) {
        float w = wgt[n] * inv;
        float4 a = *(const float4*)(sv + n * DDIM + d0);
        float4 b = *(const float4*)(sv + n * DDIM + d1);
        o0.x += w * a.x; o0.y += w * a.y; o0.z += w * a.z; o0.w += w * a.w;
        o1.x += w * b.x; o1.y += w * b.y; o1.z += w * b.z; o1.w += w * b.w;
    }
    __stcs((float4*)(out + rowOff + d0), o0);
    __stcs((float4*)(out + rowOff + d1), o1);
}

extern "C" void kernel_launch(void* const* d_in, const int* in_sizes, int n_in,
                              void* d_out, int out_size)
{
    const float* blocks     = (const float*)d_in[0];
    const float* partial    = (const float*)d_in[1];
    const float* norm_scale = (const float*)d_in[2];
    const float* proj       = (const float*)d_in[3];
    float* out              = (float*)d_out;

    const int BL = in_sizes[1] / DDIM;

    static int configured = 0;
    if (!configured) {
        cudaFuncSetAttribute(attn_residual_kernel,
                             cudaFuncAttributeMaxDynamicSharedMemorySize,
                             SMEM_BYTES);
        configured = 1;
    }

    attn_residual_kernel<<<BL, THREADS, SMEM_BYTES>>>(blocks, partial,
                                                      norm_scale, proj,
                                                      out, BL);
}

// round 13
// speedup vs baseline: 1.0481x; 1.0481x over previous
#include <cuda_runtime.h>
#include <cstdint>
#include <math.h>

// N=8 (7 completed blocks + partial), D=2048, B*L=8192 rows.
// R10 structure (grid=BL, 3 CTAs/SM, TMA bulk stage-in, 4 mbarrier phases
// of 2 slices). Warp reduction of the 16 per-thread scalars uses a packed
// butterfly (two variables folded per level): 16 SHFL total instead of 80.
#define NB 8
#define DDIM 2048
#define THREADS 256
#define ROW_BYTES (DDIM * 4)              // 8 KB per block slice
#define SMEM_BYTES (NB * DDIM * 4)        // 64 KB data stage
#define NPHASE 4

__device__ __forceinline__ void mbar_wait(unsigned int mb) {
    unsigned int done;
    asm volatile(
        "{\n\t"
        ".reg .pred p;\n\t"
        "mbarrier.try_wait.parity.acquire.cta.shared::cta.b64 p, [%1], 0;\n\t"
        "selp.b32 %0, 1, 0, p;\n\t"
        "}" : "=r"(done) : "r"(mb) : "memory");
    if (!done) {
        asm volatile(
            "{\n\t"
            ".reg .pred P1;\n\t"
            "WAIT_LOOP_%=:\n\t"
            "mbarrier.try_wait.parity.acquire.cta.shared::cta.b64 P1, [%0], 0, 0x989680;\n\t"
            "@P1 bra.uni WAIT_DONE_%=;\n\t"
            "bra.uni WAIT_LOOP_%=;\n\t"
            "WAIT_DONE_%=:\n\t"
            "}" :: "r"(mb) : "memory");
    }
}

__global__ __launch_bounds__(THREADS, 3)
void attn_residual_kernel(const float* __restrict__ blocks,     // [7, BL, D]
                          const float* __restrict__ partial,    // [BL, D]
                          const float* __restrict__ norm_scale, // [D]
                          const float* __restrict__ proj,       // [D]
                          float* __restrict__ out,              // [BL, D]
                          int BL)
{
    extern __shared__ float sv[];         // [NB][DDIM], 16B aligned
    __shared__ __align__(8) unsigned long long mbar[NPHASE];
    __shared__ float red[THREADS / 32][16];
    __shared__ float fin[16];

    const int row  = blockIdx.x;
    const int t    = threadIdx.x;
    const int lane = t & 31;
    const int warp = t >> 5;

    const size_t rowOff  = (size_t)row * DDIM;
    const size_t nStride = (size_t)BL * DDIM;

    const int d0 = t * 4;            // [0, 1024)
    const int d1 = 1024 + t * 4;     // [1024, 2048)

    unsigned int svb, mbb;
    asm("{ .reg .u64 tmp; cvta.to.shared.u64 tmp, %1; cvt.u32.u64 %0, tmp; }"
        : "=r"(svb) : "l"(sv));
    asm("{ .reg .u64 tmp; cvta.to.shared.u64 tmp, %1; cvt.u32.u64 %0, tmp; }"
        : "=r"(mbb) : "l"(&mbar[0]));

    // ---- Init mbarriers, then bulk-copy 8 contiguous 8KB slices ----
    if (t == 0) {
#pragma unroll
        for (int p = 0; p < NPHASE; p++)
            asm volatile("mbarrier.init.shared.b64 [%0], 1;"
                         :: "r"(mbb + 8u * p) : "memory");
    }
    __syncthreads();

    if (t == 0) {
#pragma unroll
        for (int p = 0; p < NPHASE; p++)
            asm volatile("mbarrier.arrive.expect_tx.shared.b64 _, [%0], %1;"
                         :: "r"(mbb + 8u * p), "r"(2 * ROW_BYTES) : "memory");
#pragma unroll
        for (int n = 0; n < NB; n++) {
            const float* src = (n < NB - 1)
                                 ? (blocks + (size_t)n * nStride + rowOff)
                                 : (partial + rowOff);
            asm volatile(
                "cp.async.bulk.shared::cluster.global.mbarrier::complete_tx::bytes"
                " [%0], [%1], %2, [%3];"
                :: "r"(svb + (unsigned)(n * ROW_BYTES)), "l"(src),
                   "r"(ROW_BYTES), "r"(mbb + 8u * (n >> 1))
                : "memory");
        }
    }

    // q[d] = proj[d] * norm_scale[d] (overlaps with bulk copies)
    float4 q0, q1;
    {
        float4 p = *(const float4*)(proj + d0);
        float4 s = *(const float4*)(norm_scale + d0);
        q0 = make_float4(p.x * s.x, p.y * s.y, p.z * s.z, p.w * s.w);
        p = *(const float4*)(proj + d1);
        s = *(const float4*)(norm_scale + d1);
        q1 = make_float4(p.x * s.x, p.y * s.y, p.z * s.z, p.w * s.w);
    }

    // v[n] = dot partial, v[8+n] = sumsq partial
    float v[16];

#define PROC(n)                                                              \
    do {                                                                     \
        float4 a = *(const float4*)(sv + (n) * DDIM + d0);                   \
        float4 b = *(const float4*)(sv + (n) * DDIM + d1);                   \
        v[n]     = q0.x * a.x + q0.y * a.y + q0.z * a.z + q0.w * a.w         \
                 + q1.x * b.x + q1.y * b.y + q1.z * b.z + q1.w * b.w;        \
        v[8+(n)] = a.x * a.x + a.y * a.y + a.z * a.z + a.w * a.w             \
                 + b.x * b.x + b.y * b.y + b.z * b.z + b.w * b.w;            \
    } while (0)

    // ---- 4 phases: wait 16KB, compute pair (overlaps later arrivals) ----
    mbar_wait(mbb + 0);  PROC(0); PROC(1);
    mbar_wait(mbb + 8);  PROC(2); PROC(3);
    mbar_wait(mbb + 16); PROC(4); PROC(5);
    mbar_wait(mbb + 24); PROC(6); PROC(7);
#undef PROC

    // ---- Packed butterfly warp reduction: 16 vars in 16 shuffles ----
    // Level 1 (xor 16): fold v[j] with v[j+8]
#pragma unroll
    for (int j = 0; j < 8; j++) {
        bool hi = (lane & 16);
        float x = hi ? v[j + 8] : v[j];
        float y = hi ? v[j] : v[j + 8];
        v[j] = x + __shfl_xor_sync(0xffffffffu, y, 16);
    }
    // Level 2 (xor 8): fold v[j] with v[j+4]
#pragma unroll
    for (int j = 0; j < 4; j++) {
        bool hi = (lane & 8);
        float x = hi ? v[j + 4] : v[j];
        float y = hi ? v[j] : v[j + 4];
        v[j] = x + __shfl_xor_sync(0xffffffffu, y, 8);
    }
    // Level 3 (xor 4): fold v[j] with v[j+2]
#pragma unroll
    for (int j = 0; j < 2; j++) {
        bool hi = (lane & 4);
        float x = hi ? v[j + 2] : v[j];
        float y = hi ? v[j] : v[j + 2];
        v[j] = x + __shfl_xor_sync(0xffffffffu, y, 4);
    }
    // Level 4 (xor 2): fold v[0] with v[1]
    float r;
    {
        bool hi = (lane & 2);
        float x = hi ? v[1] : v[0];
        float y = hi ? v[0] : v[1];
        r = x + __shfl_xor_sync(0xffffffffu, y, 2);
    }
    // Level 5 (xor 1): final fold
    r += __shfl_xor_sync(0xffffffffu, r, 1);

    // lane -> which of the 16 sums this lane now holds
    const int vi = ((lane >> 4) & 1) * 8 + ((lane >> 3) & 1) * 4
                 + ((lane >> 2) & 1) * 2 + ((lane >> 1) & 1);
    if ((lane & 1) == 0) red[warp][vi] = r;

    __syncthreads();
    if (t < 16) {
        float s = 0.f;
#pragma unroll
        for (int w = 0; w < THREADS / 32; w++) s += red[w][t];
        fin[t] = s;
    }
    __syncthreads();

    // ---- Softmax over n (redundant per-thread; trivial) ----
    float wgt[NB];
    float mx = -INFINITY;
#pragma unroll
    for (int n = 0; n < NB; n++) {
        float rms = sqrtf(fin[8 + n] * (1.0f / DDIM) + 1e-6f);
        wgt[n] = fin[n] / rms;
        mx = fmaxf(mx, wgt[n]);
    }
    float wsum = 0.f;
#pragma unroll
    for (int n = 0; n < NB; n++) {
        wgt[n] = __expf(wgt[n] - mx);
        wsum += wgt[n];
    }
    const float inv = 1.0f / wsum;

    // ---- Pass 2: weighted sum from smem; streaming store ----
    float4 o0 = make_float4(0.f, 0.f, 0.f, 0.f);
    float4 o1 = make_float4(0.f, 0.f, 0.f, 0.f);
#pragma unroll
    for (int n = 0; n < NB; n++) {
        float w = wgt[n] * inv;
        float4 a = *(const float4*)(sv + n * DDIM + d0);
        float4 b = *(const float4*)(sv + n * DDIM + d1);
        o0.x += w * a.x; o0.y += w * a.y; o0.z += w * a.z; o0.w += w * a.w;
        o1.x += w * b.x; o1.y += w * b.y; o1.z += w * b.z; o1.w += w * b.w;
    }
    __stcs((float4*)(out + rowOff + d0), o0);
    __stcs((float4*)(out + rowOff + d1), o1);
}

extern "C" void kernel_launch(void* const* d_in, const int* in_sizes, int n_in,
                              void* d_out, int out_size)
{
    const float* blocks     = (const float*)d_in[0];
    const float* partial    = (const float*)d_in[1];
    const float* norm_scale = (const float*)d_in[2];
    const float* proj       = (const float*)d_in[3];
    float* out              = (float*)d_out;

    const int BL = in_sizes[1] / DDIM;

    static int configured = 0;
    if (!configured) {
        cudaFuncSetAttribute(attn_residual_kernel,
                             cudaFuncAttributeMaxDynamicSharedMemorySize,
                             SMEM_BYTES);
        configured = 1;
    }

    attn_residual_kernel<<<BL, THREADS, SMEM_BYTES>>>(blocks, partial,
                                                      norm_scale, proj,
                                                      out, BL);
}